// round 8
// baseline (speedup 1.0000x reference)
#include <cuda_runtime.h>
#include <math.h>
#include <stdint.h>

#define CB   8
#define PP   2048
#define BB   8192
#define TK   4
#define MTOT (BB * CB)          // 65536 rows

// output offsets (elements, fp32)
#define OFF_QV   0ULL
#define OFF_QK   67108864ULL
#define OFF_IND  134217728ULL
#define OFF_DIST 134479872ULL
#define OFF_CNT  134742016ULL
#define OFF_FLAT 135004160ULL

#define NSHORT 8

// ----------------------------------------------------------------- scratch --
__device__ int    g_idx[BB * CB * TK];
__device__ int    g_short[BB * CB * NSHORT];
__device__ float  g_knorm[CB * PP];
__device__ float4 g_kT[CB * 64 * PP];      // [(c*64 + d4)*2048 + j]  (R5 dist)

__device__ float  g_A1[(size_t)MTOT * 256];
__device__ float  g_QKV[(size_t)MTOT * 768];
__device__ float  g_O[(size_t)MTOT * 256];
__device__ float  g_R1[(size_t)MTOT * 256];
__device__ float  g_A2[(size_t)MTOT * 256];
__device__ float  g_H[(size_t)MTOT * 256];
__device__ float  g_R2[(size_t)MTOT * 256];

// weight packs: float4 = (hi_k, hi_k4, lo_k, lo_k4), idx = kp*N + n,
// kp = ks*16 + k8*4 + q4 (k = ks*32 + k8*8 + q4 and k+4), kp in 0..127
__device__ float4 g_Bqkv[128 * 768];
__device__ float4 g_Bout[128 * 256];
__device__ float4 g_Bf1[128 * 256];
__device__ float4 g_Bf2[128 * 256];
__device__ float4 g_Bdec[128 * 256];

// ----------------------------------------------------------------- helpers --
__device__ __forceinline__ float warp_sum(float v) {
    #pragma unroll
    for (int o = 16; o; o >>= 1) v += __shfl_xor_sync(0xffffffffu, v, o);
    return v;
}
__device__ __forceinline__ double warp_sum_d(double v) {
    #pragma unroll
    for (int o = 16; o; o >>= 1) v += __shfl_xor_sync(0xffffffffu, v, o);
    return v;
}
__device__ __forceinline__ uint32_t to_tf32(float f) {
    uint32_t u;
    asm("cvt.rna.tf32.f32 %0, %1;" : "=r"(u) : "f"(f));
    return u;
}
__device__ __forceinline__ float to_tf32f(float f) {
    return __uint_as_float(to_tf32(f));
}
__device__ __forceinline__ void mma8(float* C, uint32_t a0, uint32_t a1,
                                     uint32_t a2, uint32_t a3,
                                     uint32_t b0, uint32_t b1) {
    asm volatile(
        "mma.sync.aligned.m16n8k8.row.col.f32.tf32.tf32.f32 "
        "{%0,%1,%2,%3}, {%4,%5,%6,%7}, {%8,%9}, {%0,%1,%2,%3};\n"
        : "+f"(C[0]), "+f"(C[1]), "+f"(C[2]), "+f"(C[3])
        : "r"(a0), "r"(a1), "r"(a2), "r"(a3), "r"(b0), "r"(b1));
}

// --------------------------------------------------------------- wsplit -----
// W [N][256] row-major -> hi/lo frag pack (B operand, col-major fragments)
__global__ void __launch_bounds__(256) wsplit_kernel(
    const float* __restrict__ w, float4* __restrict__ dst, int N) {
    int idx = blockIdx.x * 256 + threadIdx.x;
    if (idx >= 128 * N) return;
    int kp = idx / N, n = idx % N;
    int ks = kp >> 4, k8 = (kp >> 2) & 3, q4 = kp & 3;
    int k = ks * 32 + k8 * 8 + q4;
    float wa = w[(size_t)n * 256 + k];
    float wb = w[(size_t)n * 256 + k + 4];
    float ha = to_tf32f(wa), hb = to_tf32f(wb);
    dst[idx] = make_float4(ha, hb, to_tf32f(wa - ha), to_tf32f(wb - hb));
}

// ------------------------------------------------------------------- LN -----
__global__ void __launch_bounds__(256) ln_kernel(
    const float* __restrict__ src, const float* __restrict__ g,
    const float* __restrict__ b, float* __restrict__ dst) {
    int row = blockIdx.x * 8 + (threadIdx.x >> 5);
    int lane = threadIdx.x & 31;
    const float* p = src + (size_t)row * 256;
    float v[8];
    float s = 0.f;
    #pragma unroll
    for (int k = 0; k < 8; k++) { v[k] = p[lane + 32 * k]; s += v[k]; }
    s = warp_sum(s);
    float mu = s * (1.f / 256.f);
    float var = 0.f;
    #pragma unroll
    for (int k = 0; k < 8; k++) { float t = v[k] - mu; var = fmaf(t, t, var); }
    var = warp_sum(var);
    float rs = 1.0f / sqrtf(var * (1.f / 256.f) + 1e-5f);
    float* q = dst + (size_t)row * 256;
    #pragma unroll
    for (int k = 0; k < 8; k++) {
        int d = lane + 32 * k;
        q[d] = (v[k] - mu) * rs * g[d] + b[d];
    }
}

// ------------------------------------------------------------- 3xTF32 GEMM --
// C[65536 x N] = A[65536 x 256] @ B(pack) + bias, with epilogue EPI:
// 0 = plain, 1 = gelu, 2 = +res, 3 = dec (row remap (i,c)->(c,i), to out)
template<int EPI>
__global__ void __launch_bounds__(256, 2) gemm_kernel(
    const float* __restrict__ A, const float4* __restrict__ Bp, int N,
    const float* __restrict__ bias, const float* __restrict__ res,
    float* __restrict__ out)
{
    __shared__ float4 As[16 * 64];    // [k8*4+q4][mt*8+r]  16KB
    __shared__ float4 Bs[16 * 128];   // [k8*4+q4][nn]      32KB

    int tid = threadIdx.x;
    int mblk = blockIdx.x, nblk = blockIdx.y;
    int w = tid >> 5, lane = tid & 31;
    int mw = w & 1, nw = w >> 1;          // m-half (64 rows), n-quarter (32 cols)
    int q4 = lane & 3, r = lane >> 2;

    float C[4][4][4];
    #pragma unroll
    for (int a = 0; a < 4; a++)
        #pragma unroll
        for (int b2 = 0; b2 < 4; b2++)
            { C[a][b2][0] = 0.f; C[a][b2][1] = 0.f; C[a][b2][2] = 0.f; C[a][b2][3] = 0.f; }

    for (int ks = 0; ks < 8; ++ks) {
        // stage A slice [128 rows][32 k] into frag-pack
        #pragma unroll
        for (int it = 0; it < 4; ++it) {
            int idx = tid + it * 256;                 // 1024 float4 loads
            int row = idx >> 3, f4 = idx & 7;
            float4 v = *(const float4*)(A + ((size_t)(mblk * 128 + row)) * 256
                                        + ks * 32 + f4 * 4);
            int mt = row >> 4, rr = row & 15;
            int half = rr >> 3, r0 = rr & 7;
            float vals[4] = { v.x, v.y, v.z, v.w };
            #pragma unroll
            for (int e = 0; e < 4; ++e) {
                int kl = f4 * 4 + e;
                int k8 = kl >> 3, kin = kl & 7;
                int qq = kin & 3, kh = kin >> 2;
                ((float*)&As[(k8 * 4 + qq) * 64 + mt * 8 + r0])[half + 2 * kh] = vals[e];
            }
        }
        // stage B slice (already frag-packed globally)
        #pragma unroll
        for (int it = 0; it < 8; ++it) {
            int idx = tid + it * 256;                 // 2048 float4
            Bs[idx] = __ldg(Bp + (size_t)(ks * 16 + (idx >> 7)) * N
                            + nblk * 128 + (idx & 127));
        }
        __syncthreads();

        #pragma unroll
        for (int k8 = 0; k8 < 4; ++k8) {
            float4 bf[4];
            #pragma unroll
            for (int t = 0; t < 4; ++t)
                bf[t] = Bs[(k8 * 4 + q4) * 128 + nw * 32 + t * 8 + r];
            #pragma unroll
            for (int mtl = 0; mtl < 4; ++mtl) {
                float4 av = As[(k8 * 4 + q4) * 64 + (mw * 4 + mtl) * 8 + r];
                uint32_t ah0 = to_tf32(av.x), ah1 = to_tf32(av.y),
                         ah2 = to_tf32(av.z), ah3 = to_tf32(av.w);
                uint32_t al0 = to_tf32(av.x - __uint_as_float(ah0));
                uint32_t al1 = to_tf32(av.y - __uint_as_float(ah1));
                uint32_t al2 = to_tf32(av.z - __uint_as_float(ah2));
                uint32_t al3 = to_tf32(av.w - __uint_as_float(ah3));
                #pragma unroll
                for (int t = 0; t < 4; ++t) {
                    uint32_t bh0 = __float_as_uint(bf[t].x);
                    uint32_t bh1 = __float_as_uint(bf[t].y);
                    uint32_t bl0 = __float_as_uint(bf[t].z);
                    uint32_t bl1 = __float_as_uint(bf[t].w);
                    mma8(C[mtl][t], ah0, ah1, ah2, ah3, bh0, bh1);
                    mma8(C[mtl][t], ah0, ah1, ah2, ah3, bl0, bl1);
                    mma8(C[mtl][t], al0, al1, al2, al3, bh0, bh1);
                }
            }
        }
        __syncthreads();
    }

    // epilogue
    #pragma unroll
    for (int mtl = 0; mtl < 4; ++mtl) {
        #pragma unroll
        for (int t = 0; t < 4; ++t) {
            int rg = mblk * 128 + (mw * 4 + mtl) * 16 + r;
            int cg = nblk * 128 + nw * 32 + t * 8 + 2 * q4;
            float b0 = __ldg(bias + cg), b1 = __ldg(bias + cg + 1);
            float v00 = C[mtl][t][0] + b0, v01 = C[mtl][t][1] + b1;
            float v10 = C[mtl][t][2] + b0, v11 = C[mtl][t][3] + b1;
            if (EPI == 1) {
                v00 = 0.5f * v00 * (1.0f + erff(v00 * 0.70710678118654752f));
                v01 = 0.5f * v01 * (1.0f + erff(v01 * 0.70710678118654752f));
                v10 = 0.5f * v10 * (1.0f + erff(v10 * 0.70710678118654752f));
                v11 = 0.5f * v11 * (1.0f + erff(v11 * 0.70710678118654752f));
            }
            if (EPI == 2) {
                float2 r0 = *(const float2*)(res + (size_t)rg * N + cg);
                float2 r1 = *(const float2*)(res + (size_t)(rg + 8) * N + cg);
                v00 += r0.x; v01 += r0.y; v10 += r1.x; v11 += r1.y;
            }
            if (EPI == 3) {
                int ra = (rg & 7) * BB + (rg >> 3);
                int rb = ((rg + 8) & 7) * BB + ((rg + 8) >> 3);
                *(float2*)(out + (size_t)ra * 256 + cg) = make_float2(v00, v01);
                *(float2*)(out + (size_t)rb * 256 + cg) = make_float2(v10, v11);
            } else {
                *(float2*)(out + (size_t)rg * N + cg) = make_float2(v00, v01);
                *(float2*)(out + (size_t)(rg + 8) * N + cg) = make_float2(v10, v11);
            }
        }
    }
}

// ---------------------------------------------------------------- attention -
__global__ void __launch_bounds__(256) attn_kernel(const float* __restrict__ qkv) {
    __shared__ __align__(16) float qkv_s[8][768];
    __shared__ float sc[2][8][8];

    int i = blockIdx.x, tid = threadIdx.x;
    for (int idx = tid; idx < 1536; idx += 256) {
        int l = idx / 192, f4 = idx % 192;
        *(float4*)&qkv_s[l][f4 * 4] =
            *(const float4*)(qkv + ((size_t)i * 8 + l) * 768 + f4 * 4);
    }
    __syncthreads();

    if (tid < 128) {
        int h = tid >> 6, rem = tid & 63, l = rem >> 3, m = rem & 7;
        const float* q  = &qkv_s[l][h * 128];
        const float* kk = &qkv_s[m][256 + h * 128];
        float a0 = 0.f, a1 = 0.f, a2 = 0.f, a3 = 0.f;
        #pragma unroll 8
        for (int d = 0; d < 128; d += 4) {
            a0 = fmaf(q[d],     kk[d],     a0);
            a1 = fmaf(q[d + 1], kk[d + 1], a1);
            a2 = fmaf(q[d + 2], kk[d + 2], a2);
            a3 = fmaf(q[d + 3], kk[d + 3], a3);
        }
        float s = __fadd_rn(__fadd_rn(a0, a1), __fadd_rn(a2, a3));
        sc[h][l][m] = s / 11.313708498984760f;
    }
    __syncthreads();

    if (tid < 16) {
        int h = tid >> 3, l = tid & 7;
        float* row = sc[h][l];
        float mx = row[0];
        #pragma unroll
        for (int m = 1; m < 8; m++) mx = fmaxf(mx, row[m]);
        float e[8], sm = 0.f;
        #pragma unroll
        for (int m = 0; m < 8; m++) { e[m] = expf(row[m] - mx); sm += e[m]; }
        float inv = 1.f / sm;
        #pragma unroll
        for (int m = 0; m < 8; m++) row[m] = e[m] * inv;
    }
    __syncthreads();

    {
        int e = tid, h = e >> 7;
        #pragma unroll
        for (int l = 0; l < 8; l++) {
            float s = 0.f;
            #pragma unroll
            for (int m = 0; m < 8; m++) s = fmaf(sc[h][l][m], qkv_s[m][512 + e], s);
            g_O[((size_t)i * 8 + l) * 256 + e] = s;
        }
    }
}

// -------------------------------------------------- R5-proven tail kernels --
__global__ void __launch_bounds__(256) transK_kernel(const float* __restrict__ keys) {
    int idx = blockIdx.x * 256 + threadIdx.x;   // ((c*64+d4)*2048 + j)
    int j = idx & 2047, rest = idx >> 11;
    int d4 = rest & 63, c = rest >> 6;
    const float* p = keys + ((size_t)(c * PP + j)) * 256 + 4 * d4;
    g_kT[idx] = make_float4(p[0], p[1], p[2], p[3]);
}

__global__ void __launch_bounds__(256) knorm_kernel(const float* __restrict__ keys) {
    int gw = (blockIdx.x * 256 + threadIdx.x) >> 5;
    int lane = threadIdx.x & 31;
    if (gw >= CB * PP) return;
    const float* row = keys + (size_t)gw * 256;
    float s = 0.f;
    #pragma unroll
    for (int k = 0; k < 8; k++) { float t = row[lane + 32 * k]; s = fmaf(t, t, s); }
    s = warp_sum(s);
    if (lane == 0) g_knorm[gw] = s;
}

__global__ void __launch_bounds__(256) dist_kernel(const float* __restrict__ flat)
{
    __shared__ __align__(16) float F[16][256];
    __shared__ float S[16][257];
    __shared__ float mv[16][128];
    __shared__ unsigned short mi[16][128];

    int c = blockIdx.y, ib = blockIdx.x, tid = threadIdx.x;
    int i0 = ib * 16;
    int r = tid & 15, sub = tid >> 4;

    for (int idx = tid; idx < 4096; idx += 256) {
        int rr = idx >> 8, d = idx & 255;
        F[rr][d] = flat[((size_t)c * BB + i0 + rr) * 256 + d];
    }
    __syncthreads();

    float tv[NSHORT];
    int   ti[NSHORT];
    #pragma unroll
    for (int t = 0; t < NSHORT; ++t) { tv[t] = -1e30f; ti[t] = 0; }

    const float4* F4 = (const float4*)&F[0][0];

    for (int tile = 0; tile < 8; ++tile) {
        int j = tile * 256 + tid;
        const float4* kp = g_kT + (size_t)c * 64 * PP + j;
        float acc[16];
        #pragma unroll
        for (int rr = 0; rr < 16; ++rr) acc[rr] = 0.f;
        #pragma unroll 2
        for (int d4 = 0; d4 < 64; ++d4) {
            float4 k4 = __ldg(kp + (size_t)d4 * PP);
            #pragma unroll
            for (int rr = 0; rr < 16; ++rr) {
                float4 f4 = F4[rr * 64 + d4];
                acc[rr] = fmaf(f4.x, k4.x, acc[rr]);
                acc[rr] = fmaf(f4.y, k4.y, acc[rr]);
                acc[rr] = fmaf(f4.z, k4.z, acc[rr]);
                acc[rr] = fmaf(f4.w, k4.w, acc[rr]);
            }
        }
        float kn = g_knorm[c * PP + j];
        #pragma unroll
        for (int rr = 0; rr < 16; ++rr)
            S[rr][tid] = fmaf(2.f, acc[rr], -kn);
        __syncthreads();
        #pragma unroll 4
        for (int q = 0; q < 16; ++q) {
            int col = sub * 16 + q;
            float v = S[r][col];
            int jj = tile * 256 + col;
            if (v > tv[NSHORT - 1]) {
                tv[NSHORT - 1] = v; ti[NSHORT - 1] = jj;
                #pragma unroll
                for (int p = NSHORT - 1; p > 0; --p) {
                    if (tv[p] > tv[p - 1] || (tv[p] == tv[p - 1] && ti[p] < ti[p - 1])) {
                        float a = tv[p]; tv[p] = tv[p - 1]; tv[p - 1] = a;
                        int   b = ti[p]; ti[p] = ti[p - 1]; ti[p - 1] = b;
                    }
                }
            }
        }
        __syncthreads();
    }

    #pragma unroll
    for (int t = 0; t < NSHORT; ++t) {
        mv[r][sub * 8 + t] = tv[t];
        mi[r][sub * 8 + t] = (unsigned short)ti[t];
    }
    __syncthreads();

    if (tid < 16) {
        int row = tid;
        float fv[NSHORT];
        int   fi[NSHORT];
        #pragma unroll
        for (int t = 0; t < NSHORT; ++t) { fv[t] = -1e30f; fi[t] = 0; }
        for (int e = 0; e < 128; ++e) {
            float v = mv[row][e];
            int jj = (int)mi[row][e];
            if (v > fv[NSHORT - 1] || (v == fv[NSHORT - 1] && jj < fi[NSHORT - 1])) {
                fv[NSHORT - 1] = v; fi[NSHORT - 1] = jj;
                #pragma unroll
                for (int p = NSHORT - 1; p > 0; --p) {
                    if (fv[p] > fv[p - 1] || (fv[p] == fv[p - 1] && fi[p] < fi[p - 1])) {
                        float a = fv[p]; fv[p] = fv[p - 1]; fv[p - 1] = a;
                        int   b = fi[p]; fi[p] = fi[p - 1]; fi[p - 1] = b;
                    }
                }
            }
        }
        int ig = i0 + row;
        #pragma unroll
        for (int t = 0; t < NSHORT; ++t)
            g_short[((size_t)ig * 8 + c) * NSHORT + t] = fi[t];
    }
}

__global__ void __launch_bounds__(256) refine_kernel(
    const float* __restrict__ flat, const float* __restrict__ keys,
    const float* __restrict__ counter, float* __restrict__ out)
{
    int gw = (blockIdx.x * 256 + threadIdx.x) >> 5;   // row = i*8 + c
    int lane = threadIdx.x & 31;
    if (gw >= BB * CB) return;
    int i = gw >> 3, c = gw & 7;

    const float* frow = flat + ((size_t)c * BB + i) * 256;
    double f[8];
    double fn = 0.0;
    #pragma unroll
    for (int k = 0; k < 8; k++) {
        f[k] = (double)frow[lane + 32 * k];
        fn += f[k] * f[k];
    }
    fn = warp_sum_d(fn);

    float sv[NSHORT];
    int   si[NSHORT];
    float A32 = (float)fn;
    #pragma unroll
    for (int t = 0; t < NSHORT; ++t) {
        int idx = g_short[(size_t)gw * NSHORT + t];
        si[t] = idx;
        const float* krow = keys + ((size_t)c * PP + idx) * 256;
        double dot = 0.0, kn = 0.0;
        #pragma unroll
        for (int k = 0; k < 8; k++) {
            double kd = (double)krow[lane + 32 * k];
            dot += f[k] * kd;
            kn  += kd * kd;
        }
        dot = warp_sum_d(dot);
        kn  = warp_sum_d(kn);
        float B32 = 2.0f * (float)dot;
        float C32 = (float)kn;
        float t1  = __fadd_rn(A32, -B32);
        float t2  = __fadd_rn(t1, C32);
        sv[t] = -t2;
    }

    if (lane == 0) {
        #pragma unroll
        for (int a = 0; a < TK; ++a) {
            int best = a;
            #pragma unroll
            for (int b2 = a + 1; b2 < NSHORT; ++b2) {
                if (sv[b2] > sv[best] || (sv[b2] == sv[best] && si[b2] < si[best]))
                    best = b2;
            }
            float vtmp = sv[a]; sv[a] = sv[best]; sv[best] = vtmp;
            int   itmp = si[a]; si[a] = si[best]; si[best] = itmp;
            size_t o = ((size_t)i * 8 + c) * 4 + a;
            out[OFF_IND + o]  = (float)si[a];
            out[OFF_DIST + o] = sv[a];
            out[OFF_CNT + o]  = counter[c * PP + si[a]];
            g_idx[o] = si[a];
        }
    }
}

__global__ void __launch_bounds__(256) gather_kernel(
    const float* __restrict__ keys, const float* __restrict__ values,
    float* __restrict__ out)
{
    int gw = (blockIdx.x * 256 + threadIdx.x) >> 5;
    int lane = threadIdx.x & 31;
    int c = (gw >> 2) & 7;
    int idx = g_idx[gw];
    const float4* ks = (const float4*)(keys   + ((size_t)c * PP + idx) * 256);
    const float4* vs = (const float4*)(values + ((size_t)c * PP + idx) * 256);
    float4* oqk = (float4*)(out + OFF_QK) + (size_t)gw * 64;
    float4* oqv = (float4*)(out + OFF_QV) + (size_t)gw * 64;
    oqv[lane]      = vs[lane];
    oqv[lane + 32] = vs[lane + 32];
    oqk[lane]      = ks[lane];
    oqk[lane + 32] = ks[lane + 32];
}

// -----------------------------------------------------------------------------
extern "C" void kernel_launch(void* const* d_in, const int* in_sizes, int n_in,
                              void* d_out, int out_size) {
    const float* x       = (const float*)d_in[0];
    const float* keys    = (const float*)d_in[1];
    const float* values  = (const float*)d_in[2];
    const float* counter = (const float*)d_in[3];
    const float* ln1_g   = (const float*)d_in[4];
    const float* ln1_b   = (const float*)d_in[5];
    const float* w_in    = (const float*)d_in[6];
    const float* b_in    = (const float*)d_in[7];
    const float* w_out   = (const float*)d_in[8];
    const float* b_out   = (const float*)d_in[9];
    const float* ln2_g   = (const float*)d_in[10];
    const float* ln2_b   = (const float*)d_in[11];
    const float* fw1     = (const float*)d_in[12];
    const float* fb1     = (const float*)d_in[13];
    const float* fw2     = (const float*)d_in[14];
    const float* fb2     = (const float*)d_in[15];
    const float* dw      = (const float*)d_in[16];
    const float* db      = (const float*)d_in[17];
    float* out = (float*)d_out;

    float4 *bqkv, *bout, *bf1p, *bf2p, *bdec;
    cudaGetSymbolAddress((void**)&bqkv, g_Bqkv);
    cudaGetSymbolAddress((void**)&bout, g_Bout);
    cudaGetSymbolAddress((void**)&bf1p, g_Bf1);
    cudaGetSymbolAddress((void**)&bf2p, g_Bf2);
    cudaGetSymbolAddress((void**)&bdec, g_Bdec);
    float *a1, *qkv, *o, *r1, *a2, *h, *r2;
    cudaGetSymbolAddress((void**)&a1, g_A1);
    cudaGetSymbolAddress((void**)&qkv, g_QKV);
    cudaGetSymbolAddress((void**)&o, g_O);
    cudaGetSymbolAddress((void**)&r1, g_R1);
    cudaGetSymbolAddress((void**)&a2, g_A2);
    cudaGetSymbolAddress((void**)&h, g_H);
    cudaGetSymbolAddress((void**)&r2, g_R2);

    wsplit_kernel<<<(128 * 768 + 255) / 256, 256>>>(w_in,  bqkv, 768);
    wsplit_kernel<<<(128 * 256 + 255) / 256, 256>>>(w_out, bout, 256);
    wsplit_kernel<<<(128 * 256 + 255) / 256, 256>>>(fw1,   bf1p, 256);
    wsplit_kernel<<<(128 * 256 + 255) / 256, 256>>>(fw2,   bf2p, 256);
    wsplit_kernel<<<(128 * 256 + 255) / 256, 256>>>(dw,    bdec, 256);
    transK_kernel<<<CB * 64 * PP / 256, 256>>>(keys);
    knorm_kernel<<<2048, 256>>>(keys);

    // encoder pipeline
    ln_kernel<<<8192, 256>>>(x, ln1_g, ln1_b, a1);
    gemm_kernel<0><<<dim3(512, 6), 256>>>(a1, bqkv, 768, b_in, nullptr, qkv);
    attn_kernel<<<8192, 256>>>(qkv);
    gemm_kernel<2><<<dim3(512, 2), 256>>>(o, bout, 256, b_out, x, r1);
    ln_kernel<<<8192, 256>>>(r1, ln2_g, ln2_b, a2);
    gemm_kernel<1><<<dim3(512, 2), 256>>>(a2, bf1p, 256, fb1, nullptr, h);
    gemm_kernel<2><<<dim3(512, 2), 256>>>(h, bf2p, 256, fb2, r1, r2);
    gemm_kernel<3><<<dim3(512, 2), 256>>>(r2, bdec, 256, db, nullptr, out + OFF_FLAT);

    // selection + gather (R5-proven)
    dist_kernel<<<dim3(BB / 16, CB), 256>>>(out + OFF_FLAT);
    refine_kernel<<<BB * CB / 8, 256>>>(out + OFF_FLAT, keys, counter, out);
    gather_kernel<<<32768, 256>>>(keys, values, out);
}

// round 9
// speedup vs baseline: 1.4460x; 1.4460x over previous
#include <cuda_runtime.h>
#include <math.h>
#include <stdint.h>

#define CB   8
#define PP   2048
#define DKx  256
#define BB   8192
#define TK   4

// output offsets (elements, fp32)
#define OFF_QV   0ULL
#define OFF_QK   67108864ULL
#define OFF_IND  134217728ULL
#define OFF_DIST 134479872ULL
#define OFF_CNT  134742016ULL
#define OFF_FLAT 135004160ULL

#define NSHORT 8

__device__ int    g_idx[BB * CB * TK];
__device__ int    g_short[BB * CB * NSHORT];
__device__ float  g_knorm[CB * PP];
// transposed keys: coalesced float4 over contraction dim [(c*64 + d4)*2048 + j]
__device__ float4 g_kT[CB * 64 * PP];
// transposed weights for enc (coalesced float4 over contraction dim)
__device__ float4 g_wT_in[64 * 768];       // [d4*768 + col]
__device__ float4 g_wT_out[64 * 256];
__device__ float4 g_wT_f1[64 * 256];
__device__ float4 g_wT_f2[64 * 256];
__device__ float4 g_wT_dec[64 * 256];

__device__ __forceinline__ float warp_sum(float v) {
    #pragma unroll
    for (int o = 16; o; o >>= 1) v += __shfl_xor_sync(0xffffffffu, v, o);
    return v;
}
__device__ __forceinline__ double warp_sum_d(double v) {
    #pragma unroll
    for (int o = 16; o; o >>= 1) v += __shfl_xor_sync(0xffffffffu, v, o);
    return v;
}

// Kahan compensated add (intrinsics defeat contraction/reassociation)
__device__ __forceinline__ void kadd(float& s, float& c, float v) {
    float y = __fsub_rn(v, c);
    float t = __fadd_rn(s, y);
    c = __fsub_rn(__fsub_rn(t, s), y);
    s = t;
}

// ------------------------------------------------------------- transposes ---
__global__ void __launch_bounds__(256) transW_kernel(
    const float* __restrict__ src, float4* __restrict__ dst, int NC) {
    int idx = blockIdx.x * 256 + threadIdx.x;           // idx = d4*NC + col
    if (idx >= 64 * NC) return;
    int d4 = idx / NC, col = idx % NC;
    const float* p = src + (size_t)col * 256 + 4 * d4;
    dst[idx] = make_float4(p[0], p[1], p[2], p[3]);
}

__global__ void __launch_bounds__(256) transK_kernel(const float* __restrict__ keys) {
    int idx = blockIdx.x * 256 + threadIdx.x;           // ((c*64+d4)*2048 + j)
    int j = idx & 2047, rest = idx >> 11;
    int d4 = rest & 63, c = rest >> 6;
    const float* p = keys + ((size_t)(c * PP + j)) * 256 + 4 * d4;
    g_kT[idx] = make_float4(p[0], p[1], p[2], p[3]);
}

// ----------------------------------------------------------------- LN -------
__device__ __forceinline__ void ln_rows(float (*src)[DKx], float (*dst)[DKx],
                                        const float* __restrict__ g,
                                        const float* __restrict__ b, int tid) {
    int w = tid >> 5, lane = tid & 31;
    float* row = src[w];
    float s = 0.f;
    #pragma unroll
    for (int k = 0; k < 8; k++) s += row[lane + 32 * k];
    s = warp_sum(s);
    float mu = s * (1.f / 256.f);
    float v = 0.f;
    #pragma unroll
    for (int k = 0; k < 8; k++) { float t = row[lane + 32 * k] - mu; v = fmaf(t, t, v); }
    v = warp_sum(v);
    float rs = 1.0f / sqrtf(v * (1.f / 256.f) + 1e-5f);
    #pragma unroll
    for (int k = 0; k < 8; k++) {
        int d = lane + 32 * k;
        dst[w][d] = (row[d] - mu) * rs * g[d] + b[d];
    }
}

// Compensated 8-row dot: 16-MAC chunks (serial FMA chain), Kahan across chunks.
__device__ __forceinline__ void dot8k(const float4* __restrict__ A4, int stride4,
                                      const float4* __restrict__ wT4, int NC, int col,
                                      float* out) {
    float s[8], c[8];
    #pragma unroll
    for (int l = 0; l < 8; l++) { s[l] = 0.f; c[l] = 0.f; }
    #pragma unroll 2
    for (int g = 0; g < 16; ++g) {
        float4 w0 = __ldg(wT4 + (size_t)(4 * g + 0) * NC + col);
        float4 w1 = __ldg(wT4 + (size_t)(4 * g + 1) * NC + col);
        float4 w2 = __ldg(wT4 + (size_t)(4 * g + 2) * NC + col);
        float4 w3 = __ldg(wT4 + (size_t)(4 * g + 3) * NC + col);
        #pragma unroll
        for (int l = 0; l < 8; l++) {
            const float4 a0 = A4[l * stride4 + 4 * g + 0];
            const float4 a1 = A4[l * stride4 + 4 * g + 1];
            const float4 a2 = A4[l * stride4 + 4 * g + 2];
            const float4 a3 = A4[l * stride4 + 4 * g + 3];
            float ch = a0.x * w0.x;
            ch = fmaf(a0.y, w0.y, ch); ch = fmaf(a0.z, w0.z, ch); ch = fmaf(a0.w, w0.w, ch);
            ch = fmaf(a1.x, w1.x, ch); ch = fmaf(a1.y, w1.y, ch);
            ch = fmaf(a1.z, w1.z, ch); ch = fmaf(a1.w, w1.w, ch);
            ch = fmaf(a2.x, w2.x, ch); ch = fmaf(a2.y, w2.y, ch);
            ch = fmaf(a2.z, w2.z, ch); ch = fmaf(a2.w, w2.w, ch);
            ch = fmaf(a3.x, w3.x, ch); ch = fmaf(a3.y, w3.y, ch);
            ch = fmaf(a3.z, w3.z, ch); ch = fmaf(a3.w, w3.w, ch);
            kadd(s[l], c[l], ch);
        }
    }
    #pragma unroll
    for (int l = 0; l < 8; l++) out[l] = __fadd_rn(s[l], c[l]);
}

// ---------------------------------------------------------------- Kernel A ---
__global__ void __launch_bounds__(256) enc_kernel(
    const float* __restrict__ x,
    const float* __restrict__ ln1_g, const float* __restrict__ ln1_b,
    const float* __restrict__ b_in,  const float* __restrict__ b_out,
    const float* __restrict__ ln2_g, const float* __restrict__ ln2_b,
    const float* __restrict__ fb1,   const float* __restrict__ fb2,
    const float* __restrict__ db,
    float* __restrict__ out_flat)
{
    __shared__ __align__(16) float flat_s[8][DKx];
    __shared__ __align__(16) float a_s[8][DKx];
    __shared__ __align__(16) float qkv_s[8][768];
    __shared__ float sc[2][8][8];

    int i = blockIdx.x, tid = threadIdx.x;

    for (int idx = tid; idx < 2048; idx += 256)
        flat_s[idx >> 8][idx & 255] = x[((size_t)i * 8 + (idx >> 8)) * 256 + (idx & 255)];
    __syncthreads();

    ln_rows(flat_s, a_s, ln1_g, ln1_b, tid);
    __syncthreads();

    // qkv = h0 @ w_in^T + b_in
    for (int ch = 0; ch < 3; ++ch) {
        int col = ch * 256 + tid;
        float res[8];
        dot8k((const float4*)&a_s[0][0], 64, g_wT_in, 768, col, res);
        float bi = b_in[col];
        #pragma unroll
        for (int l = 0; l < 8; l++) qkv_s[l][col] = __fadd_rn(res[l], bi);
    }
    __syncthreads();

    // scores (fp32, 4-way split accumulators)
    if (tid < 128) {
        int h = tid >> 6, rem = tid & 63, l = rem >> 3, m = rem & 7;
        const float* q  = &qkv_s[l][h * 128];
        const float* kk = &qkv_s[m][256 + h * 128];
        float a0 = 0.f, a1 = 0.f, a2 = 0.f, a3 = 0.f;
        #pragma unroll 8
        for (int d = 0; d < 128; d += 4) {
            a0 = fmaf(q[d],     kk[d],     a0);
            a1 = fmaf(q[d + 1], kk[d + 1], a1);
            a2 = fmaf(q[d + 2], kk[d + 2], a2);
            a3 = fmaf(q[d + 3], kk[d + 3], a3);
        }
        float s = __fadd_rn(__fadd_rn(a0, a1), __fadd_rn(a2, a3));
        sc[h][l][m] = s / 11.313708498984760f;
    }
    __syncthreads();

    // softmax
    if (tid < 16) {
        int h = tid >> 3, l = tid & 7;
        float* row = sc[h][l];
        float mx = row[0];
        #pragma unroll
        for (int m = 1; m < 8; m++) mx = fmaxf(mx, row[m]);
        float e[8], sm = 0.f;
        #pragma unroll
        for (int m = 0; m < 8; m++) { e[m] = expf(row[m] - mx); sm += e[m]; }
        float inv = 1.f / sm;
        #pragma unroll
        for (int m = 0; m < 8; m++) row[m] = e[m] * inv;
    }
    __syncthreads();

    // o = a @ v
    {
        int e = tid, h = e >> 7;
        #pragma unroll
        for (int l = 0; l < 8; l++) {
            float s = 0.f;
            #pragma unroll
            for (int m = 0; m < 8; m++) s = fmaf(sc[h][l][m], qkv_s[m][512 + e], s);
            a_s[l][e] = s;
        }
    }
    __syncthreads();

    // proj + residual
    {
        int col = tid;
        float res[8];
        dot8k((const float4*)&a_s[0][0], 64, g_wT_out, 256, col, res);
        float bo = b_out[col];
        #pragma unroll
        for (int l = 0; l < 8; l++)
            flat_s[l][col] = __fadd_rn(__fadd_rn(res[l], bo), flat_s[l][col]);
    }
    __syncthreads();

    ln_rows(flat_s, a_s, ln2_g, ln2_b, tid);
    __syncthreads();

    // ffn1 + gelu (exact, fp32 erff)
    {
        int col = tid;
        float res[8];
        dot8k((const float4*)&a_s[0][0], 64, g_wT_f1, 256, col, res);
        float b1 = fb1[col];
        #pragma unroll
        for (int l = 0; l < 8; l++) {
            float u = __fadd_rn(res[l], b1);
            qkv_s[l][col] = 0.5f * u * (1.0f + erff(u * 0.70710678118654752f));
        }
    }
    __syncthreads();

    // ffn2 + residual
    {
        int col = tid;
        float res[8];
        dot8k((const float4*)&qkv_s[0][0], 192, g_wT_f2, 256, col, res);
        float b2 = fb2[col];
        #pragma unroll
        for (int l = 0; l < 8; l++)
            flat_s[l][col] = __fadd_rn(__fadd_rn(res[l], b2), flat_s[l][col]);
    }
    __syncthreads();

    // dec -> flatten
    {
        int col = tid;
        float res[8];
        dot8k((const float4*)&flat_s[0][0], 64, g_wT_dec, 256, col, res);
        float bd = db[col];
        #pragma unroll
        for (int l = 0; l < 8; l++)
            out_flat[((size_t)l * BB + i) * 256 + col] = __fadd_rn(res[l], bd);
    }
}

// ---------------------------------------------------------------- knorm ------
__global__ void __launch_bounds__(256) knorm_kernel(const float* __restrict__ keys) {
    int gw = (blockIdx.x * 256 + threadIdx.x) >> 5;
    int lane = threadIdx.x & 31;
    if (gw >= CB * PP) return;
    const float* row = keys + (size_t)gw * 256;
    float s = 0.f;
    #pragma unroll
    for (int k = 0; k < 8; k++) { float t = row[lane + 32 * k]; s = fmaf(t, t, s); }
    s = warp_sum(s);
    if (lane == 0) g_knorm[gw] = s;
}

// ---------------------------------------------------------------- Kernel B ---
// Fused distance GEMM + top-8 shortlist; 2-way j register blocking: each thread
// computes columns j and j+256, reusing each shared-F load for 2 FMA vectors.
__global__ void __launch_bounds__(256) dist_kernel(const float* __restrict__ flat)
{
    __shared__ __align__(16) float F[16][256];
    __shared__ float S[16][517];
    __shared__ float mv[16][128];
    __shared__ unsigned short mi[16][128];

    int c = blockIdx.y, ib = blockIdx.x, tid = threadIdx.x;
    int i0 = ib * 16;
    int r = tid & 15, sub = tid >> 4;

    for (int idx = tid; idx < 1024; idx += 256) {
        int rr = idx >> 6, d4 = idx & 63;
        *(float4*)&F[rr][d4 * 4] =
            *(const float4*)(flat + ((size_t)c * BB + i0 + rr) * 256 + d4 * 4);
    }
    __syncthreads();

    float tv[NSHORT];
    int   ti[NSHORT];
    #pragma unroll
    for (int t = 0; t < NSHORT; ++t) { tv[t] = -1e30f; ti[t] = 0; }

    const float4* F4 = (const float4*)&F[0][0];

    for (int tile = 0; tile < 4; ++tile) {
        int j = tile * 512 + tid;
        const float4* kp = g_kT + (size_t)c * 64 * PP + j;
        float acc0[16], acc1[16];
        #pragma unroll
        for (int rr = 0; rr < 16; ++rr) { acc0[rr] = 0.f; acc1[rr] = 0.f; }
        #pragma unroll 2
        for (int d4 = 0; d4 < 64; ++d4) {
            float4 ka = __ldg(kp + (size_t)d4 * PP);
            float4 kb = __ldg(kp + (size_t)d4 * PP + 256);
            #pragma unroll
            for (int rr = 0; rr < 16; ++rr) {
                float4 f4 = F4[rr * 64 + d4];
                acc0[rr] = fmaf(f4.x, ka.x, acc0[rr]);
                acc0[rr] = fmaf(f4.y, ka.y, acc0[rr]);
                acc0[rr] = fmaf(f4.z, ka.z, acc0[rr]);
                acc0[rr] = fmaf(f4.w, ka.w, acc0[rr]);
                acc1[rr] = fmaf(f4.x, kb.x, acc1[rr]);
                acc1[rr] = fmaf(f4.y, kb.y, acc1[rr]);
                acc1[rr] = fmaf(f4.z, kb.z, acc1[rr]);
                acc1[rr] = fmaf(f4.w, kb.w, acc1[rr]);
            }
        }
        float kn0 = g_knorm[c * PP + j];
        float kn1 = g_knorm[c * PP + j + 256];
        #pragma unroll
        for (int rr = 0; rr < 16; ++rr) {
            S[rr][tid]       = fmaf(2.f, acc0[rr], -kn0);
            S[rr][tid + 256] = fmaf(2.f, acc1[rr], -kn1);
        }
        __syncthreads();
        // per-row top-8 scan: thread (r,sub) scans 32 ascending columns
        #pragma unroll 4
        for (int q = 0; q < 32; ++q) {
            int col = sub * 32 + q;
            float v = S[r][col];
            int jj = tile * 512 + col;
            if (v > tv[NSHORT - 1]) {
                tv[NSHORT - 1] = v; ti[NSHORT - 1] = jj;
                #pragma unroll
                for (int p = NSHORT - 1; p > 0; --p) {
                    if (tv[p] > tv[p - 1] || (tv[p] == tv[p - 1] && ti[p] < ti[p - 1])) {
                        float a = tv[p]; tv[p] = tv[p - 1]; tv[p - 1] = a;
                        int   b = ti[p]; ti[p] = ti[p - 1]; ti[p - 1] = b;
                    }
                }
            }
        }
        __syncthreads();
    }

    // merge 16 per-thread lists per row
    #pragma unroll
    for (int t = 0; t < NSHORT; ++t) {
        mv[r][sub * 8 + t] = tv[t];
        mi[r][sub * 8 + t] = (unsigned short)ti[t];
    }
    __syncthreads();

    if (tid < 16) {
        int row = tid;
        float fv[NSHORT];
        int   fi[NSHORT];
        #pragma unroll
        for (int t = 0; t < NSHORT; ++t) { fv[t] = -1e30f; fi[t] = 0; }
        for (int e = 0; e < 128; ++e) {
            float v = mv[row][e];
            int jj = (int)mi[row][e];
            if (v > fv[NSHORT - 1] || (v == fv[NSHORT - 1] && jj < fi[NSHORT - 1])) {
                fv[NSHORT - 1] = v; fi[NSHORT - 1] = jj;
                #pragma unroll
                for (int p = NSHORT - 1; p > 0; --p) {
                    if (fv[p] > fv[p - 1] || (fv[p] == fv[p - 1] && fi[p] < fi[p - 1])) {
                        float a = fv[p]; fv[p] = fv[p - 1]; fv[p - 1] = a;
                        int   b = fi[p]; fi[p] = fi[p - 1]; fi[p - 1] = b;
                    }
                }
            }
        }
        int ig = i0 + row;
        #pragma unroll
        for (int t = 0; t < NSHORT; ++t)
            g_short[((size_t)ig * 8 + c) * NSHORT + t] = fi[t];
    }
}

// ---------------------------------------------------------------- refine -----
// fp64 exact terms + fp32 tensor-boundary emulation of the reference dist,
// tie-break by lower index (jax.lax.top_k).
__global__ void __launch_bounds__(256) refine_kernel(
    const float* __restrict__ flat, const float* __restrict__ keys,
    const float* __restrict__ counter, float* __restrict__ out)
{
    int gw = (blockIdx.x * 256 + threadIdx.x) >> 5;   // row = i*8 + c
    int lane = threadIdx.x & 31;
    if (gw >= BB * CB) return;
    int i = gw >> 3, c = gw & 7;

    const float* frow = flat + ((size_t)c * BB + i) * 256;
    double f[8];
    double fn = 0.0;
    #pragma unroll
    for (int k = 0; k < 8; k++) {
        f[k] = (double)frow[lane + 32 * k];
        fn += f[k] * f[k];
    }
    fn = warp_sum_d(fn);

    float sv[NSHORT];
    int   si[NSHORT];
    float A32 = (float)fn;
    #pragma unroll
    for (int t = 0; t < NSHORT; ++t) {
        int idx = g_short[(size_t)gw * NSHORT + t];
        si[t] = idx;
        const float* krow = keys + ((size_t)c * PP + idx) * 256;
        double dot = 0.0, kn = 0.0;
        #pragma unroll
        for (int k = 0; k < 8; k++) {
            double kd = (double)krow[lane + 32 * k];
            dot += f[k] * kd;
            kn  += kd * kd;
        }
        dot = warp_sum_d(dot);
        kn  = warp_sum_d(kn);
        float B32 = 2.0f * (float)dot;
        float C32 = (float)kn;
        float t1  = __fadd_rn(A32, -B32);
        float t2  = __fadd_rn(t1, C32);
        sv[t] = -t2;
    }

    if (lane == 0) {
        #pragma unroll
        for (int a = 0; a < TK; ++a) {
            int best = a;
            #pragma unroll
            for (int b2 = a + 1; b2 < NSHORT; ++b2) {
                if (sv[b2] > sv[best] || (sv[b2] == sv[best] && si[b2] < si[best]))
                    best = b2;
            }
            float vtmp = sv[a]; sv[a] = sv[best]; sv[best] = vtmp;
            int   itmp = si[a]; si[a] = si[best]; si[best] = itmp;
            size_t o = ((size_t)i * 8 + c) * 4 + a;
            out[OFF_IND + o]  = (float)si[a];
            out[OFF_DIST + o] = sv[a];
            out[OFF_CNT + o]  = counter[c * PP + si[a]];
            g_idx[o] = si[a];
        }
    }
}

// ---------------------------------------------------------------- Kernel C ---
__global__ void __launch_bounds__(256) gather_kernel(
    const float* __restrict__ keys, const float* __restrict__ values,
    float* __restrict__ out)
{
    int gw = (blockIdx.x * 256 + threadIdx.x) >> 5;
    int lane = threadIdx.x & 31;
    int c = (gw >> 2) & 7;
    int idx = g_idx[gw];
    const float4* ks = (const float4*)(keys   + ((size_t)c * PP + idx) * 256);
    const float4* vs = (const float4*)(values + ((size_t)c * PP + idx) * 256);
    float4* oqk = (float4*)(out + OFF_QK) + (size_t)gw * 64;
    float4* oqv = (float4*)(out + OFF_QV) + (size_t)gw * 64;
    oqv[lane]      = vs[lane];
    oqv[lane + 32] = vs[lane + 32];
    oqk[lane]      = ks[lane];
    oqk[lane + 32] = ks[lane + 32];
}

// -----------------------------------------------------------------------------
extern "C" void kernel_launch(void* const* d_in, const int* in_sizes, int n_in,
                              void* d_out, int out_size) {
    const float* x       = (const float*)d_in[0];
    const float* keys    = (const float*)d_in[1];
    const float* values  = (const float*)d_in[2];
    const float* counter = (const float*)d_in[3];
    const float* ln1_g   = (const float*)d_in[4];
    const float* ln1_b   = (const float*)d_in[5];
    const float* w_in    = (const float*)d_in[6];
    const float* b_in    = (const float*)d_in[7];
    const float* w_out   = (const float*)d_in[8];
    const float* b_out   = (const float*)d_in[9];
    const float* ln2_g   = (const float*)d_in[10];
    const float* ln2_b   = (const float*)d_in[11];
    const float* fw1     = (const float*)d_in[12];
    const float* fb1     = (const float*)d_in[13];
    const float* fw2     = (const float*)d_in[14];
    const float* fb2     = (const float*)d_in[15];
    const float* dw      = (const float*)d_in[16];
    const float* db      = (const float*)d_in[17];
    float* out = (float*)d_out;

    float4* wt_in;  cudaGetSymbolAddress((void**)&wt_in,  g_wT_in);
    float4* wt_out; cudaGetSymbolAddress((void**)&wt_out, g_wT_out);
    float4* wt_f1;  cudaGetSymbolAddress((void**)&wt_f1,  g_wT_f1);
    float4* wt_f2;  cudaGetSymbolAddress((void**)&wt_f2,  g_wT_f2);
    float4* wt_dec; cudaGetSymbolAddress((void**)&wt_dec, g_wT_dec);

    // launches 1-5 (enc is launch 6 -> captured by ncu -s 5 -c 1)
    transW_kernel<<<(64 * 768 + 255) / 256, 256>>>(w_in,  wt_in,  768);
    transW_kernel<<<(64 * 256 + 255) / 256, 256>>>(w_out, wt_out, 256);
    transW_kernel<<<(64 * 256 + 255) / 256, 256>>>(fw1,   wt_f1,  256);
    transW_kernel<<<(64 * 256 + 255) / 256, 256>>>(fw2,   wt_f2,  256);
    transW_kernel<<<(64 * 256 + 255) / 256, 256>>>(dw,    wt_dec, 256);

    enc_kernel<<<BB, 256>>>(x, ln1_g, ln1_b, b_in, b_out,
                            ln2_g, ln2_b, fb1, fb2, db, out + OFF_FLAT);

    transK_kernel<<<CB * 64 * PP / 256, 256>>>(keys);
    knorm_kernel<<<2048, 256>>>(keys);

    dist_kernel<<<dim3(BB / 16, CB), 256>>>(out + OFF_FLAT);
    refine_kernel<<<BB * CB / 8, 256>>>(out + OFF_FLAT, keys, counter, out);
    gather_kernel<<<32768, 256>>>(keys, values, out);
}

// round 10
// speedup vs baseline: 1.5234x; 1.0535x over previous
#include <cuda_runtime.h>
#include <math.h>
#include <stdint.h>

#define CB   8
#define PP   2048
#define DKx  256
#define BB   8192
#define TK   4

// output offsets (elements, fp32)
#define OFF_QV   0ULL
#define OFF_QK   67108864ULL
#define OFF_IND  134217728ULL
#define OFF_DIST 134479872ULL
#define OFF_CNT  134742016ULL
#define OFF_FLAT 135004160ULL

#define NSHORT 8

typedef unsigned long long ull;

__device__ int    g_idx[BB * CB * TK];
__device__ int    g_short[BB * CB * NSHORT];
__device__ float  g_knorm[CB * PP];
// transposed keys: coalesced float4 over contraction dim [(c*64 + d4)*2048 + j]
__device__ float4 g_kT[CB * 64 * PP];
// transposed weights for enc (coalesced float4 over contraction dim)
__device__ float4 g_wT_in[64 * 768];       // [d4*768 + col]
__device__ float4 g_wT_out[64 * 256];
__device__ float4 g_wT_f1[64 * 256];
__device__ float4 g_wT_f2[64 * 256];
__device__ float4 g_wT_dec[64 * 256];

// --------------------------------------------------------- packed f32x2 ----
__device__ __forceinline__ ull pack2(float lo, float hi) {
    ull r; asm("mov.b64 %0,{%1,%2};" : "=l"(r) : "f"(lo), "f"(hi)); return r;
}
__device__ __forceinline__ void unpack2(float& lo, float& hi, ull v) {
    asm("mov.b64 {%0,%1},%2;" : "=f"(lo), "=f"(hi) : "l"(v));
}
__device__ __forceinline__ ull fma2(ull a, ull b, ull c) {
    ull d; asm("fma.rn.f32x2 %0,%1,%2,%3;" : "=l"(d) : "l"(a), "l"(b), "l"(c)); return d;
}
__device__ __forceinline__ ull add2(ull a, ull b) {
    ull d; asm("add.rn.f32x2 %0,%1,%2;" : "=l"(d) : "l"(a), "l"(b)); return d;
}
__device__ __forceinline__ ull mul2(ull a, ull b) {
    ull d; asm("mul.rn.f32x2 %0,%1,%2;" : "=l"(d) : "l"(a), "l"(b)); return d;
}
// Kahan on packed pairs; fma2(x,-1,y) rounds identically to sub(y,x).
__device__ __forceinline__ void kadd2(ull& s, ull& c, ull v) {
    const ull neg1 = 0xBF800000BF800000ULL;
    ull y = fma2(c, neg1, v);
    ull t = add2(s, y);
    c = fma2(y, neg1, fma2(s, neg1, t));
    s = t;
}

__device__ __forceinline__ float warp_sum(float v) {
    #pragma unroll
    for (int o = 16; o; o >>= 1) v += __shfl_xor_sync(0xffffffffu, v, o);
    return v;
}
__device__ __forceinline__ double warp_sum_d(double v) {
    #pragma unroll
    for (int o = 16; o; o >>= 1) v += __shfl_xor_sync(0xffffffffu, v, o);
    return v;
}

// ------------------------------------------------------------- transposes ---
__global__ void __launch_bounds__(256) transW_kernel(
    const float* __restrict__ src, float4* __restrict__ dst, int NC) {
    int idx = blockIdx.x * 256 + threadIdx.x;           // idx = d4*NC + col
    if (idx >= 64 * NC) return;
    int d4 = idx / NC, col = idx % NC;
    const float* p = src + (size_t)col * 256 + 4 * d4;
    dst[idx] = make_float4(p[0], p[1], p[2], p[3]);
}

__global__ void __launch_bounds__(256) transK_kernel(const float* __restrict__ keys) {
    int idx = blockIdx.x * 256 + threadIdx.x;           // ((c*64+d4)*2048 + j)
    int j = idx & 2047, rest = idx >> 11;
    int d4 = rest & 63, c = rest >> 6;
    const float* p = keys + ((size_t)(c * PP + j)) * 256 + 4 * d4;
    g_kT[idx] = make_float4(p[0], p[1], p[2], p[3]);
}

// -------------------------------------------------------- LN (pair layout) --
// pair layout: buf[d*8 + pair*2 + comp], pair = row>>1, comp = row&1
__device__ __forceinline__ void ln_pair(const float* __restrict__ src,
                                        float* __restrict__ dst,
                                        const float* __restrict__ g,
                                        const float* __restrict__ b, int tid) {
    int w = tid >> 5, lane = tid & 31;
    int off = (w >> 1) * 2 + (w & 1);
    float v[8];
    float s = 0.f;
    #pragma unroll
    for (int k = 0; k < 8; k++) { v[k] = src[(lane + 32 * k) * 8 + off]; s += v[k]; }
    s = warp_sum(s);
    float mu = s * (1.f / 256.f);
    float var = 0.f;
    #pragma unroll
    for (int k = 0; k < 8; k++) { float t = v[k] - mu; var = fmaf(t, t, var); }
    var = warp_sum(var);
    float rs = 1.0f / sqrtf(var * (1.f / 256.f) + 1e-5f);
    #pragma unroll
    for (int k = 0; k < 8; k++) {
        int d = lane + 32 * k;
        dst[d * 8 + off] = (v[k] - mu) * rs * g[d] + b[d];
    }
}

// Packed compensated dot: 4 row-pairs per column; 16-MAC Kahan chunks.
// Ap: ulonglong2 view of pair buffer (2 per d). Same accumulation order as R9.
__device__ __forceinline__ void dot8kp(const ulonglong2* __restrict__ Ap,
                                       const float4* __restrict__ wT4, int NC, int col,
                                       ull* out) {
    ull s[4], c[4];
    #pragma unroll
    for (int p = 0; p < 4; p++) { s[p] = 0ULL; c[p] = 0ULL; }
    #pragma unroll 2
    for (int g = 0; g < 16; ++g) {
        float4 w[4];
        w[0] = __ldg(wT4 + (size_t)(4 * g + 0) * NC + col);
        w[1] = __ldg(wT4 + (size_t)(4 * g + 1) * NC + col);
        w[2] = __ldg(wT4 + (size_t)(4 * g + 2) * NC + col);
        w[3] = __ldg(wT4 + (size_t)(4 * g + 3) * NC + col);
        ull ch0, ch1, ch2, ch3;
        {
            ull wp = pack2(w[0].x, w[0].x);
            ulonglong2 a01 = Ap[(g * 16) * 2 + 0];
            ulonglong2 a23 = Ap[(g * 16) * 2 + 1];
            ch0 = mul2(a01.x, wp); ch1 = mul2(a01.y, wp);
            ch2 = mul2(a23.x, wp); ch3 = mul2(a23.y, wp);
        }
        #pragma unroll
        for (int dd = 1; dd < 16; ++dd) {
            float we = (&w[dd >> 2].x)[dd & 3];
            ull wp = pack2(we, we);
            int d = g * 16 + dd;
            ulonglong2 a01 = Ap[d * 2 + 0];
            ulonglong2 a23 = Ap[d * 2 + 1];
            ch0 = fma2(a01.x, wp, ch0); ch1 = fma2(a01.y, wp, ch1);
            ch2 = fma2(a23.x, wp, ch2); ch3 = fma2(a23.y, wp, ch3);
        }
        kadd2(s[0], c[0], ch0); kadd2(s[1], c[1], ch1);
        kadd2(s[2], c[2], ch2); kadd2(s[3], c[3], ch3);
    }
    #pragma unroll
    for (int p = 0; p < 4; p++) out[p] = add2(s[p], c[p]);
}

// ---------------------------------------------------------------- Kernel A ---
__global__ void __launch_bounds__(256) enc_kernel(
    const float* __restrict__ x,
    const float* __restrict__ ln1_g, const float* __restrict__ ln1_b,
    const float* __restrict__ b_in,  const float* __restrict__ b_out,
    const float* __restrict__ ln2_g, const float* __restrict__ ln2_b,
    const float* __restrict__ fb1,   const float* __restrict__ fb2,
    const float* __restrict__ db,
    float* __restrict__ out_flat)
{
    __shared__ __align__(16) float flatP[256 * 8];   // pair layout residual
    __shared__ __align__(16) float aP[256 * 8];      // pair layout LN/attn-o
    __shared__ __align__(16) float qkv_s[8][768];    // row layout (attention)
    __shared__ float sc[2][8][8];

    float* hP = &qkv_s[0][0];    // ffn hidden (pair layout), aliases dead qkv

    int i = blockIdx.x, tid = threadIdx.x;

    // stage x into pair layout
    for (int idx = tid; idx < 512; idx += 256) {
        int l = idx >> 6, d4 = idx & 63;
        float4 v = *(const float4*)(x + ((size_t)i * 8 + l) * 256 + 4 * d4);
        int off = (l >> 1) * 2 + (l & 1);
        flatP[(4 * d4 + 0) * 8 + off] = v.x;
        flatP[(4 * d4 + 1) * 8 + off] = v.y;
        flatP[(4 * d4 + 2) * 8 + off] = v.z;
        flatP[(4 * d4 + 3) * 8 + off] = v.w;
    }
    __syncthreads();

    ln_pair(flatP, aP, ln1_g, ln1_b, tid);
    __syncthreads();

    // qkv = h0 @ w_in^T + b_in  (row-major out for attention)
    for (int ch = 0; ch < 3; ++ch) {
        int col = ch * 256 + tid;
        ull res[4];
        dot8kp((const ulonglong2*)aP, g_wT_in, 768, col, res);
        float bi = b_in[col];
        #pragma unroll
        for (int p = 0; p < 4; p++) {
            float lo, hi; unpack2(lo, hi, res[p]);
            qkv_s[2 * p][col]     = __fadd_rn(lo, bi);
            qkv_s[2 * p + 1][col] = __fadd_rn(hi, bi);
        }
    }
    __syncthreads();

    // scores (fp32, 4-way split accumulators)
    if (tid < 128) {
        int h = tid >> 6, rem = tid & 63, l = rem >> 3, m = rem & 7;
        const float* q  = &qkv_s[l][h * 128];
        const float* kk = &qkv_s[m][256 + h * 128];
        float a0 = 0.f, a1 = 0.f, a2 = 0.f, a3 = 0.f;
        #pragma unroll 8
        for (int d = 0; d < 128; d += 4) {
            a0 = fmaf(q[d],     kk[d],     a0);
            a1 = fmaf(q[d + 1], kk[d + 1], a1);
            a2 = fmaf(q[d + 2], kk[d + 2], a2);
            a3 = fmaf(q[d + 3], kk[d + 3], a3);
        }
        float s = __fadd_rn(__fadd_rn(a0, a1), __fadd_rn(a2, a3));
        sc[h][l][m] = s / 11.313708498984760f;
    }
    __syncthreads();

    // softmax
    if (tid < 16) {
        int h = tid >> 3, l = tid & 7;
        float* row = sc[h][l];
        float mx = row[0];
        #pragma unroll
        for (int m = 1; m < 8; m++) mx = fmaxf(mx, row[m]);
        float e[8], sm = 0.f;
        #pragma unroll
        for (int m = 0; m < 8; m++) { e[m] = expf(row[m] - mx); sm += e[m]; }
        float inv = 1.f / sm;
        #pragma unroll
        for (int m = 0; m < 8; m++) row[m] = e[m] * inv;
    }
    __syncthreads();

    // o = a @ v -> aP (pair layout)
    {
        int e = tid, h = e >> 7;
        float sl[8];
        #pragma unroll
        for (int l = 0; l < 8; l++) {
            float s = 0.f;
            #pragma unroll
            for (int m = 0; m < 8; m++) s = fmaf(sc[h][l][m], qkv_s[m][512 + e], s);
            sl[l] = s;
        }
        __syncthreads();   // qkv_s reads done before hP alias writes later
        #pragma unroll
        for (int p = 0; p < 4; p++)
            *(ull*)&aP[e * 8 + 2 * p] = pack2(sl[2 * p], sl[2 * p + 1]);
    }
    __syncthreads();

    // proj + residual (pair)
    {
        int col = tid;
        ull res[4];
        dot8kp((const ulonglong2*)aP, g_wT_out, 256, col, res);
        float bo = b_out[col];
        ull bop = pack2(bo, bo);
        #pragma unroll
        for (int p = 0; p < 4; p++) {
            ull old = *(ull*)&flatP[col * 8 + 2 * p];
            *(ull*)&flatP[col * 8 + 2 * p] = add2(add2(res[p], bop), old);
        }
    }
    __syncthreads();

    ln_pair(flatP, aP, ln2_g, ln2_b, tid);
    __syncthreads();

    // ffn1 + gelu -> hP (pair)
    {
        int col = tid;
        ull res[4];
        dot8kp((const ulonglong2*)aP, g_wT_f1, 256, col, res);
        float b1 = fb1[col];
        #pragma unroll
        for (int p = 0; p < 4; p++) {
            float lo, hi; unpack2(lo, hi, res[p]);
            float u0 = __fadd_rn(lo, b1), u1 = __fadd_rn(hi, b1);
            float g0 = 0.5f * u0 * (1.0f + erff(u0 * 0.70710678118654752f));
            float g1 = 0.5f * u1 * (1.0f + erff(u1 * 0.70710678118654752f));
            *(ull*)&hP[col * 8 + 2 * p] = pack2(g0, g1);
        }
    }
    __syncthreads();

    // ffn2 + residual (pair)
    {
        int col = tid;
        ull res[4];
        dot8kp((const ulonglong2*)hP, g_wT_f2, 256, col, res);
        float b2 = fb2[col];
        ull b2p = pack2(b2, b2);
        #pragma unroll
        for (int p = 0; p < 4; p++) {
            ull old = *(ull*)&flatP[col * 8 + 2 * p];
            *(ull*)&flatP[col * 8 + 2 * p] = add2(add2(res[p], b2p), old);
        }
    }
    __syncthreads();

    // dec -> flatten (global, row-major (c,i))
    {
        int col = tid;
        ull res[4];
        dot8kp((const ulonglong2*)flatP, g_wT_dec, 256, col, res);
        float bd = db[col];
        #pragma unroll
        for (int p = 0; p < 4; p++) {
            float lo, hi; unpack2(lo, hi, res[p]);
            out_flat[((size_t)(2 * p) * BB + i) * 256 + col]     = __fadd_rn(lo, bd);
            out_flat[((size_t)(2 * p + 1) * BB + i) * 256 + col] = __fadd_rn(hi, bd);
        }
    }
}

// ---------------------------------------------------------------- knorm ------
__global__ void __launch_bounds__(256) knorm_kernel(const float* __restrict__ keys) {
    int gw = (blockIdx.x * 256 + threadIdx.x) >> 5;
    int lane = threadIdx.x & 31;
    if (gw >= CB * PP) return;
    const float* row = keys + (size_t)gw * 256;
    float s = 0.f;
    #pragma unroll
    for (int k = 0; k < 8; k++) { float t = row[lane + 32 * k]; s = fmaf(t, t, s); }
    s = warp_sum(s);
    if (lane == 0) g_knorm[gw] = s;
}

// ---------------------------------------------------------------- Kernel B ---
// Fused distance GEMM (packed f32x2, 8 row-pairs) + 2-way j blocking + top-8.
__global__ void __launch_bounds__(256) dist_kernel(const float* __restrict__ flat)
{
    __shared__ __align__(16) float Fp[256 * 16];   // pair layout [d][8 pairs]
    __shared__ float S[16][517];
    __shared__ float mv[16][128];
    __shared__ unsigned short mi[16][128];

    int c = blockIdx.y, ib = blockIdx.x, tid = threadIdx.x;
    int i0 = ib * 16;
    int r = tid & 15, sub = tid >> 4;

    for (int idx = tid; idx < 1024; idx += 256) {
        int rr = idx >> 6, d4 = idx & 63;
        float4 v = *(const float4*)(flat + ((size_t)c * BB + i0 + rr) * 256 + d4 * 4);
        int off = (rr >> 1) * 2 + (rr & 1);
        Fp[(4 * d4 + 0) * 16 + off] = v.x;
        Fp[(4 * d4 + 1) * 16 + off] = v.y;
        Fp[(4 * d4 + 2) * 16 + off] = v.z;
        Fp[(4 * d4 + 3) * 16 + off] = v.w;
    }
    __syncthreads();

    float tv[NSHORT];
    int   ti[NSHORT];
    #pragma unroll
    for (int t = 0; t < NSHORT; ++t) { tv[t] = -1e30f; ti[t] = 0; }

    const ulonglong2* Fp2 = (const ulonglong2*)Fp;   // 4 per d

    for (int tile = 0; tile < 4; ++tile) {
        int j = tile * 512 + tid;
        const float4* kp = g_kT + (size_t)c * 64 * PP + j;
        ull acc0[8], acc1[8];
        #pragma unroll
        for (int p = 0; p < 8; ++p) { acc0[p] = 0ULL; acc1[p] = 0ULL; }
        #pragma unroll 2
        for (int d4 = 0; d4 < 64; ++d4) {
            float4 ka = __ldg(kp + (size_t)d4 * PP);
            float4 kb = __ldg(kp + (size_t)d4 * PP + 256);
            #pragma unroll
            for (int e = 0; e < 4; ++e) {
                int d = 4 * d4 + e;
                float kae = (&ka.x)[e], kbe = (&kb.x)[e];
                ull ka2 = pack2(kae, kae);
                ull kb2 = pack2(kbe, kbe);
                ulonglong2 f01 = Fp2[d * 4 + 0];
                ulonglong2 f23 = Fp2[d * 4 + 1];
                ulonglong2 f45 = Fp2[d * 4 + 2];
                ulonglong2 f67 = Fp2[d * 4 + 3];
                acc0[0] = fma2(f01.x, ka2, acc0[0]); acc0[1] = fma2(f01.y, ka2, acc0[1]);
                acc0[2] = fma2(f23.x, ka2, acc0[2]); acc0[3] = fma2(f23.y, ka2, acc0[3]);
                acc0[4] = fma2(f45.x, ka2, acc0[4]); acc0[5] = fma2(f45.y, ka2, acc0[5]);
                acc0[6] = fma2(f67.x, ka2, acc0[6]); acc0[7] = fma2(f67.y, ka2, acc0[7]);
                acc1[0] = fma2(f01.x, kb2, acc1[0]); acc1[1] = fma2(f01.y, kb2, acc1[1]);
                acc1[2] = fma2(f23.x, kb2, acc1[2]); acc1[3] = fma2(f23.y, kb2, acc1[3]);
                acc1[4] = fma2(f45.x, kb2, acc1[4]); acc1[5] = fma2(f45.y, kb2, acc1[5]);
                acc1[6] = fma2(f67.x, kb2, acc1[6]); acc1[7] = fma2(f67.y, kb2, acc1[7]);
            }
        }
        float kn0 = g_knorm[c * PP + j];
        float kn1 = g_knorm[c * PP + j + 256];
        #pragma unroll
        for (int p = 0; p < 8; ++p) {
            float a, b2v;
            unpack2(a, b2v, acc0[p]);
            S[2 * p][tid]     = fmaf(2.f, a,   -kn0);
            S[2 * p + 1][tid] = fmaf(2.f, b2v, -kn0);
            unpack2(a, b2v, acc1[p]);
            S[2 * p][tid + 256]     = fmaf(2.f, a,   -kn1);
            S[2 * p + 1][tid + 256] = fmaf(2.f, b2v, -kn1);
        }
        __syncthreads();
        // per-row top-8 scan: thread (r,sub) scans 32 ascending columns
        #pragma unroll 4
        for (int q = 0; q < 32; ++q) {
            int col = sub * 32 + q;
            float v = S[r][col];
            int jj = tile * 512 + col;
            if (v > tv[NSHORT - 1]) {
                tv[NSHORT - 1] = v; ti[NSHORT - 1] = jj;
                #pragma unroll
                for (int p = NSHORT - 1; p > 0; --p) {
                    if (tv[p] > tv[p - 1] || (tv[p] == tv[p - 1] && ti[p] < ti[p - 1])) {
                        float a = tv[p]; tv[p] = tv[p - 1]; tv[p - 1] = a;
                        int   b = ti[p]; ti[p] = ti[p - 1]; ti[p - 1] = b;
                    }
                }
            }
        }
        __syncthreads();
    }

    // merge 16 per-thread lists per row
    #pragma unroll
    for (int t = 0; t < NSHORT; ++t) {
        mv[r][sub * 8 + t] = tv[t];
        mi[r][sub * 8 + t] = (unsigned short)ti[t];
    }
    __syncthreads();

    if (tid < 16) {
        int row = tid;
        float fv[NSHORT];
        int   fi[NSHORT];
        #pragma unroll
        for (int t = 0; t < NSHORT; ++t) { fv[t] = -1e30f; fi[t] = 0; }
        for (int e = 0; e < 128; ++e) {
            float v = mv[row][e];
            int jj = (int)mi[row][e];
            if (v > fv[NSHORT - 1] || (v == fv[NSHORT - 1] && jj < fi[NSHORT - 1])) {
                fv[NSHORT - 1] = v; fi[NSHORT - 1] = jj;
                #pragma unroll
                for (int p = NSHORT - 1; p > 0; --p) {
                    if (fv[p] > fv[p - 1] || (fv[p] == fv[p - 1] && fi[p] < fi[p - 1])) {
                        float a = fv[p]; fv[p] = fv[p - 1]; fv[p - 1] = a;
                        int   b = fi[p]; fi[p] = fi[p - 1]; fi[p - 1] = b;
                    }
                }
            }
        }
        int ig = i0 + row;
        #pragma unroll
        for (int t = 0; t < NSHORT; ++t)
            g_short[((size_t)ig * 8 + c) * NSHORT + t] = fi[t];
    }
}

// ---------------------------------------------------------------- refine -----
__global__ void __launch_bounds__(256) refine_kernel(
    const float* __restrict__ flat, const float* __restrict__ keys,
    const float* __restrict__ counter, float* __restrict__ out)
{
    int gw = (blockIdx.x * 256 + threadIdx.x) >> 5;   // row = i*8 + c
    int lane = threadIdx.x & 31;
    if (gw >= BB * CB) return;
    int i = gw >> 3, c = gw & 7;

    const float* frow = flat + ((size_t)c * BB + i) * 256;
    double f[8];
    double fn = 0.0;
    #pragma unroll
    for (int k = 0; k < 8; k++) {
        f[k] = (double)frow[lane + 32 * k];
        fn += f[k] * f[k];
    }
    fn = warp_sum_d(fn);

    float sv[NSHORT];
    int   si[NSHORT];
    float A32 = (float)fn;
    #pragma unroll
    for (int t = 0; t < NSHORT; ++t) {
        int idx = g_short[(size_t)gw * NSHORT + t];
        si[t] = idx;
        const float* krow = keys + ((size_t)c * PP + idx) * 256;
        double dot = 0.0, kn = 0.0;
        #pragma unroll
        for (int k = 0; k < 8; k++) {
            double kd = (double)krow[lane + 32 * k];
            dot += f[k] * kd;
            kn  += kd * kd;
        }
        dot = warp_sum_d(dot);
        kn  = warp_sum_d(kn);
        float B32 = 2.0f * (float)dot;
        float C32 = (float)kn;
        float t1  = __fadd_rn(A32, -B32);
        float t2  = __fadd_rn(t1, C32);
        sv[t] = -t2;
    }

    if (lane == 0) {
        #pragma unroll
        for (int a = 0; a < TK; ++a) {
            int best = a;
            #pragma unroll
            for (int b2 = a + 1; b2 < NSHORT; ++b2) {
                if (sv[b2] > sv[best] || (sv[b2] == sv[best] && si[b2] < si[best]))
                    best = b2;
            }
            float vtmp = sv[a]; sv[a] = sv[best]; sv[best] = vtmp;
            int   itmp = si[a]; si[a] = si[best]; si[best] = itmp;
            size_t o = ((size_t)i * 8 + c) * 4 + a;
            out[OFF_IND + o]  = (float)si[a];
            out[OFF_DIST + o] = sv[a];
            out[OFF_CNT + o]  = counter[c * PP + si[a]];
            g_idx[o] = si[a];
        }
    }
}

// ---------------------------------------------------------------- Kernel C ---
__global__ void __launch_bounds__(256) gather_kernel(
    const float* __restrict__ keys, const float* __restrict__ values,
    float* __restrict__ out)
{
    int gw = (blockIdx.x * 256 + threadIdx.x) >> 5;
    int lane = threadIdx.x & 31;
    int c = (gw >> 2) & 7;
    int idx = g_idx[gw];
    const float4* ks = (const float4*)(keys   + ((size_t)c * PP + idx) * 256);
    const float4* vs = (const float4*)(values + ((size_t)c * PP + idx) * 256);
    float4* oqk = (float4*)(out + OFF_QK) + (size_t)gw * 64;
    float4* oqv = (float4*)(out + OFF_QV) + (size_t)gw * 64;
    oqv[lane]      = vs[lane];
    oqv[lane + 32] = vs[lane + 32];
    oqk[lane]      = ks[lane];
    oqk[lane + 32] = ks[lane + 32];
}

// -----------------------------------------------------------------------------
extern "C" void kernel_launch(void* const* d_in, const int* in_sizes, int n_in,
                              void* d_out, int out_size) {
    const float* x       = (const float*)d_in[0];
    const float* keys    = (const float*)d_in[1];
    const float* values  = (const float*)d_in[2];
    const float* counter = (const float*)d_in[3];
    const float* ln1_g   = (const float*)d_in[4];
    const float* ln1_b   = (const float*)d_in[5];
    const float* w_in    = (const float*)d_in[6];
    const float* b_in    = (const float*)d_in[7];
    const float* w_out   = (const float*)d_in[8];
    const float* b_out   = (const float*)d_in[9];
    const float* ln2_g   = (const float*)d_in[10];
    const float* ln2_b   = (const float*)d_in[11];
    const float* fw1     = (const float*)d_in[12];
    const float* fb1     = (const float*)d_in[13];
    const float* fw2     = (const float*)d_in[14];
    const float* fb2     = (const float*)d_in[15];
    const float* dw      = (const float*)d_in[16];
    const float* db      = (const float*)d_in[17];
    float* out = (float*)d_out;

    float4* wt_in;  cudaGetSymbolAddress((void**)&wt_in,  g_wT_in);
    float4* wt_out; cudaGetSymbolAddress((void**)&wt_out, g_wT_out);
    float4* wt_f1;  cudaGetSymbolAddress((void**)&wt_f1,  g_wT_f1);
    float4* wt_f2;  cudaGetSymbolAddress((void**)&wt_f2,  g_wT_f2);
    float4* wt_dec; cudaGetSymbolAddress((void**)&wt_dec, g_wT_dec);

    // launches 1-5 (enc is launch 6 -> captured by ncu -s 5 -c 1)
    transW_kernel<<<(64 * 768 + 255) / 256, 256>>>(w_in,  wt_in,  768);
    transW_kernel<<<(64 * 256 + 255) / 256, 256>>>(w_out, wt_out, 256);
    transW_kernel<<<(64 * 256 + 255) / 256, 256>>>(fw1,   wt_f1,  256);
    transW_kernel<<<(64 * 256 + 255) / 256, 256>>>(fw2,   wt_f2,  256);
    transW_kernel<<<(64 * 256 + 255) / 256, 256>>>(dw,    wt_dec, 256);

    enc_kernel<<<BB, 256>>>(x, ln1_g, ln1_b, b_in, b_out,
                            ln2_g, ln2_b, fb1, fb2, db, out + OFF_FLAT);

    transK_kernel<<<CB * 64 * PP / 256, 256>>>(keys);
    knorm_kernel<<<2048, 256>>>(keys);

    dist_kernel<<<dim3(BB / 16, CB), 256>>>(out + OFF_FLAT);
    refine_kernel<<<BB * CB / 8, 256>>>(out + OFF_FLAT, keys, counter, out);
    gather_kernel<<<32768, 256>>>(keys, values, out);
}